// round 5
// baseline (speedup 1.0000x reference)
#include <cuda_runtime.h>
#include <math.h>

typedef unsigned long long ull;

#define TT   512
#define BBAT 64
#define DD   128
#define UU   256
#define G3   768
#define NBLK 128
#define TPB  256
#define CH   8
#define WST  258          // Wdup / Ah2 row stride in f32x2 units (pad 2)

// ---------------- device scratch ----------------
__device__ float g_xg[(size_t)BBAT * TT * G3];   // x @ W_in + bias0
__device__ float g_basep[2][BBAT][CH][UU];       // chunk-base partials (2 j-halves)
__device__ unsigned g_barcnt = 0;
__device__ volatile unsigned g_bargen = 0;

// packed f32x2 helpers (Blackwell; ptxas never emits FFMA2 from C++)
#define FMA2(acc, a, b) \
    asm("fma.rn.f32x2 %0, %1, %2, %0;" : "+l"(acc) : "l"(a), "l"(b))
#define ADD2(acc, a) \
    asm("add.rn.f32x2 %0, %1, %0;" : "+l"(acc) : "l"(a))
__device__ __forceinline__ ull pack2(float x, float y) {
    ull r; asm("mov.b64 %0, {%1, %2};" : "=l"(r) : "f"(x), "f"(y)); return r;
}
__device__ __forceinline__ void unpack2(ull v, float& x, float& y) {
    asm("mov.b64 {%0, %1}, %2;" : "=f"(x), "=f"(y) : "l"(v));
}

// Grid barrier: all 128 CTAs resident (1/SM). Per-thread __threadfence
// (release, gpu scope) before arrival; volatile flag + fence on wake.
// All cross-block data is read via __ldcg (L2 = coherence point); __ldg
// is used only for never-rewritten data (cond/x/W/g_xg after stage0).
__device__ __forceinline__ void grid_sync() {
    __threadfence();
    __syncthreads();
    if (threadIdx.x == 0) {
        unsigned g = g_bargen;
        if (atomicAdd(&g_barcnt, 1u) == NBLK - 1) {
            atomicExch(&g_barcnt, 0u);
            __threadfence();
            g_bargen = g + 1;
        } else {
            while (g_bargen == g) { __nanosleep(64); }
        }
        __threadfence();
    }
    __syncthreads();
}

// smem layout (float offsets)
#define WD_OFF   0        // Wdup: 24 rows x 258 f32x2 = 12384 f (49536 B)
#define BIG_OFF  12384    // 8192 f union: stage0 As / chunk Hs / step Ah2
#define CS_OFF   20576    // 256 f  chunk cond tile
#define CSM_OFF  20832    // 128 f  per-step cond stage
#define GH_OFF   20960    // 384 f  h-side preactivations
#define SMEM_F   21344    // 85376 B

__global__ void __launch_bounds__(TPB, 1) dag_rnn_kernel(
    const float* __restrict__ x,     // (B,T,D)
    const float* __restrict__ cond,  // (B,T,T)
    const float* __restrict__ Win,   // (D,3U)
    const float* __restrict__ Wrec,  // (U,3U)
    const float* __restrict__ bias,  // (2,3U)
    float* __restrict__ out)         // (B,T,U) == H storage
{
    extern __shared__ __align__(16) float smem[];
    ull*   Wd  = (ull*)(smem + WD_OFF);   // [c][k] = {w,w}
    float* BIG = smem + BIG_OFF;
    ull*   Ah2 = (ull*)BIG;               // [bp][k] = {A[2bp,k], A[2bp+1,k]}
    float* Cs  = smem + CS_OFF;
    float* Csm = smem + CSM_OFF;
    float* Gh  = smem + GH_OFF;

    const int tid = threadIdx.x;
    const int blk = blockIdx.x;

    const int b0 = (blk >> 5) * 16;    // batch tile
    const int u0 = (blk & 31) * 8;     // u tile

    // hg-GEMM identity (tid<192): 8 batch-pairs x 24 cols
    const int c  = tid % 24;
    const int bp = tid / 24;
    const int gcol = (c >> 3) * UU + u0 + (c & 7);
    float bh = 0.f;
    if (tid < 192) bh = bias[G3 + gcol];

    // ---- preload Wrec slice, duplicated pairs: Wd[c][k] = {w,w} ----
    for (int idx = tid; idx < 24 * UU; idx += TPB) {
        int cc = idx >> 8, k = idx & 255;
        int colc = (cc >> 3) * UU + u0 + (cc & 7);
        float w = Wrec[(size_t)k * G3 + colc];
        Wd[cc * WST + k] = pack2(w, w);
    }

    // ================= stage 0: g_xg = x @ Win + bias0 =================
    {
        float* As = BIG;                       // 32 x 128
        const float bz  = bias[tid];
        const float br  = bias[UU + tid];
        const float bhh = bias[2 * UU + tid];
        const int row0 = blk * 256;
        for (int rt = 0; rt < 8; ++rt) {
            const int rbase = row0 + rt * 32;
            __syncthreads();
            for (int idx = tid; idx < 32 * DD; idx += TPB)
                As[idx] = x[(size_t)rbase * DD + idx];
            __syncthreads();
            for (int rs = 0; rs < 4; ++rs) {
                float a0[8], a1[8], a2[8];
                #pragma unroll
                for (int r = 0; r < 8; ++r) { a0[r] = 0.f; a1[r] = 0.f; a2[r] = 0.f; }
                const float* asr = As + (rs * 8) * DD;
                #pragma unroll 4
                for (int k = 0; k < DD; ++k) {
                    float w0 = __ldg(&Win[(size_t)k * G3 + tid]);
                    float w1 = __ldg(&Win[(size_t)k * G3 + UU + tid]);
                    float w2 = __ldg(&Win[(size_t)k * G3 + 2 * UU + tid]);
                    #pragma unroll
                    for (int r = 0; r < 8; ++r) {
                        float a = asr[r * DD + k];
                        a0[r] += a * w0; a1[r] += a * w1; a2[r] += a * w2;
                    }
                }
                #pragma unroll
                for (int r = 0; r < 8; ++r) {
                    size_t ro = (size_t)(rbase + rs * 8 + r) * G3;
                    g_xg[ro + tid]          = a0[r] + bz;
                    g_xg[ro + UU + tid]     = a1[r] + br;
                    g_xg[ro + 2 * UU + tid] = a2[r] + bhh;
                }
            }
        }
    }
    grid_sync();

    const float invT = 1.0f / (float)TT;

    for (int c0 = 0; c0 < TT; c0 += CH) {
        // ---------- chunk-base GEMM: 64 batches x 2 j-halves ----------
        if (c0 > 0) {
            float* Hs = BIG;                   // up to 32 x 256
            const int cb   = blk >> 1;
            const int jh   = blk & 1;
            const int kb   = c0 >> 1;
            const int jbeg = jh * kb;
            const float* hrow = out  + ((size_t)cb * TT + jbeg) * UU;
            const float* crow = cond + ((size_t)cb * TT + c0) * TT + jbeg;

            float acc[2][8];
            #pragma unroll
            for (int a = 0; a < 2; ++a)
                #pragma unroll
                for (int q = 0; q < 8; ++q) acc[a][q] = 0.f;

            const int lg = tid >> 5;
            const int ug = tid & 31;

            for (int jt = 0; jt < kb; jt += 32) {
                const int jn = (kb - jt < 32) ? (kb - jt) : 32;
                __syncthreads();
                for (int idx = tid; idx < jn * UU; idx += TPB)
                    Hs[idx] = __ldcg(&hrow[(size_t)jt * UU + idx]);
                {
                    int l = tid >> 5, jj = tid & 31;
                    if (jj < jn)
                        Cs[jj * CH + l] = __ldg(&crow[(size_t)l * TT + jt + jj]);
                }
                __syncthreads();
                if (tid < 128) {
                    for (int jj = 0; jj < jn; ++jj) {
                        float cv0 = Cs[jj * CH + lg];
                        float cv1 = Cs[jj * CH + lg + 4];
                        const float4* h4 = (const float4*)&Hs[jj * UU + ug * 8];
                        float4 ha = h4[0], hb2 = h4[1];
                        acc[0][0] += cv0 * ha.x;  acc[0][1] += cv0 * ha.y;
                        acc[0][2] += cv0 * ha.z;  acc[0][3] += cv0 * ha.w;
                        acc[0][4] += cv0 * hb2.x; acc[0][5] += cv0 * hb2.y;
                        acc[0][6] += cv0 * hb2.z; acc[0][7] += cv0 * hb2.w;
                        acc[1][0] += cv1 * ha.x;  acc[1][1] += cv1 * ha.y;
                        acc[1][2] += cv1 * ha.z;  acc[1][3] += cv1 * ha.w;
                        acc[1][4] += cv1 * hb2.x; acc[1][5] += cv1 * hb2.y;
                        acc[1][6] += cv1 * hb2.z; acc[1][7] += cv1 * hb2.w;
                    }
                }
            }
            if (tid < 128) {
                #pragma unroll
                for (int li = 0; li < 2; ++li) {
                    const int l = lg + li * 4;
                    float* dst = &g_basep[jh][cb][l][ug * 8];
                    ((float4*)dst)[0] = make_float4(acc[li][0], acc[li][1],
                                                    acc[li][2], acc[li][3]);
                    ((float4*)dst)[1] = make_float4(acc[li][4], acc[li][5],
                                                    acc[li][6], acc[li][7]);
                }
            }
            grid_sync();
        }

        // ---------------- sequential steps within chunk ----------------
        for (int l = 0; l < CH; ++l) {
            const int i = c0 + l;

            // stage correction conds: Csm[jj*16+bb], jj<l
            {
                const int jj = tid >> 4, bb = tid & 15;
                if (jj < l)
                    Csm[tid] = __ldg(&cond[((size_t)(b0 + bb) * TT + i) * TT + c0 + jj]);
            }
            __syncthreads();

            // ---- correction + base -> Ah2 (128 u-pairs x 2 bb-halves) ----
            {
                const int u2  = tid & 127;     // u pair: (2u2, 2u2+1)
                const int bbh = tid >> 7;      // bb in [8*bbh, 8*bbh+8)
                float2 acc[8];
                if (c0 > 0) {
                    #pragma unroll
                    for (int r = 0; r < 8; ++r) {
                        const int bb = bbh * 8 + r;
                        float2 p0 = __ldcg((const float2*)&g_basep[0][b0 + bb][l][2 * u2]);
                        float2 p1 = __ldcg((const float2*)&g_basep[1][b0 + bb][l][2 * u2]);
                        acc[r].x = p0.x + p1.x;
                        acc[r].y = p0.y + p1.y;
                    }
                } else {
                    #pragma unroll
                    for (int r = 0; r < 8; ++r) acc[r] = make_float2(0.f, 0.f);
                }
                for (int jj = 0; jj < l; ++jj) {
                    #pragma unroll
                    for (int r = 0; r < 8; ++r) {
                        const int bb = bbh * 8 + r;
                        float cv = Csm[jj * 16 + bb];
                        float2 h = __ldcg((const float2*)
                            &out[((size_t)(b0 + bb) * TT + c0 + jj) * UU + 2 * u2]);
                        acc[r].x += cv * h.x;
                        acc[r].y += cv * h.y;
                    }
                }
                float* ahf = (float*)Ah2;
                #pragma unroll
                for (int r = 0; r < 8; ++r) {
                    const int bb = bbh * 8 + r;
                    const int wo = ((bb >> 1) * WST) * 2 + (bb & 1);
                    ahf[wo + 2 * (2 * u2)]     = acc[r].x * invT;
                    ahf[wo + 2 * (2 * u2 + 1)] = acc[r].y * invT;
                }
            }
            __syncthreads();

            // ---- hg = next @ Wrec via packed FFMA2 (192 threads) ----
            if (tid < 192) {
                const ull* wa = Wd  + c  * WST;
                const ull* aa = Ah2 + bp * WST;
                ull acc0 = 0ull, acc1 = 0ull, acc2 = 0ull, acc3 = 0ull;
                #pragma unroll 8
                for (int k2 = 0; k2 < 64; ++k2) {
                    ulonglong2 w0 = ((const ulonglong2*)wa)[2 * k2];
                    ulonglong2 a0 = ((const ulonglong2*)aa)[2 * k2];
                    ulonglong2 w1 = ((const ulonglong2*)wa)[2 * k2 + 1];
                    ulonglong2 a1 = ((const ulonglong2*)aa)[2 * k2 + 1];
                    FMA2(acc0, a0.x, w0.x);
                    FMA2(acc1, a0.y, w0.y);
                    FMA2(acc2, a1.x, w1.x);
                    FMA2(acc3, a1.y, w1.y);
                }
                ADD2(acc0, acc1);
                ADD2(acc2, acc3);
                ADD2(acc0, acc2);
                float g0, g1;
                unpack2(acc0, g0, g1);
                Gh[(2 * bp)     * 24 + c] = g0 + bh;
                Gh[(2 * bp + 1) * 24 + c] = g1 + bh;
            }
            __syncthreads();

            // ---- gates + output (16b x 8u = 128 threads) ----
            if (tid < 128) {
                const int uq = tid & 7, bb = tid >> 3;
                const size_t xo = ((size_t)(b0 + bb) * TT + i) * G3 + u0 + uq;
                float xz = __ldg(&g_xg[xo]);
                float xr = __ldg(&g_xg[xo + UU]);
                float xh = __ldg(&g_xg[xo + 2 * UU]);
                float hz = Gh[bb * 24 + uq];
                float hr = Gh[bb * 24 + 8 + uq];
                float hh = Gh[bb * 24 + 16 + uq];
                float z  = 1.0f / (1.0f + __expf(-(xz + hz)));
                float r  = 1.0f / (1.0f + __expf(-(xr + hr)));
                float hc = tanhf(xh + r * hh);
                float h  = ((const float*)Ah2)[((bb >> 1) * WST + u0 + uq) * 2 + (bb & 1)];
                out[((size_t)(b0 + bb) * TT + i) * UU + u0 + uq]
                    = z * h + (1.0f - z) * hc;
            }
            grid_sync();
        }
    }
}

extern "C" void kernel_launch(void* const* d_in, const int* in_sizes, int n_in,
                              void* d_out, int out_size) {
    const float* x    = (const float*)d_in[0];
    const float* cond = (const float*)d_in[1];
    const float* Win  = (const float*)d_in[2];
    const float* Wrec = (const float*)d_in[3];
    const float* bias = (const float*)d_in[4];
    float* out = (float*)d_out;

    const int smem_bytes = SMEM_F * sizeof(float);
    static bool attr_set = false;
    if (!attr_set) {
        cudaFuncSetAttribute(dag_rnn_kernel,
                             cudaFuncAttributeMaxDynamicSharedMemorySize, smem_bytes);
        attr_set = true;
    }
    dag_rnn_kernel<<<NBLK, TPB, smem_bytes>>>(x, cond, Win, Wrec, bias, out);
}

// round 6
// speedup vs baseline: 1.1085x; 1.1085x over previous
#include <cuda_runtime.h>
#include <math.h>

typedef unsigned long long ull;

#define TT   512
#define BBAT 64
#define DD   128
#define UU   256
#define G3   768
#define NBLK 128
#define TPB  256
#define CH   8
#define WST  258          // Wdup / Ah2 row stride in f32x2 units (pad 2)
#define NGRP 4
#define GBLK 32           // blocks per group

// ---------------- device scratch ----------------
__device__ float g_xg[(size_t)BBAT * TT * G3];   // x @ W_in + bias0
__device__ float g_basep[2][BBAT][CH][UU];       // chunk-base partials (2 j-halves)
// per-group barrier state, 256B-strided to dodge L2 hash pairing
__device__ unsigned g_barcnt[NGRP * 64];
__device__ volatile unsigned g_bargen[NGRP * 64];

// packed f32x2 helpers (Blackwell; ptxas never emits FFMA2 from C++)
#define FMA2(acc, a, b) \
    asm("fma.rn.f32x2 %0, %1, %2, %0;" : "+l"(acc) : "l"(a), "l"(b))
#define ADD2(acc, a) \
    asm("add.rn.f32x2 %0, %1, %0;" : "+l"(acc) : "l"(a))
__device__ __forceinline__ ull pack2(float x, float y) {
    ull r; asm("mov.b64 %0, {%1, %2};" : "=l"(r) : "f"(x), "f"(y)); return r;
}
__device__ __forceinline__ void unpack2(ull v, float& x, float& y) {
    asm("mov.b64 {%0, %1}, %2;" : "=f"(x), "=f"(y) : "l"(v));
}
__device__ __forceinline__ float tanh_fast(float v) {
    float y; asm("tanh.approx.f32 %0, %1;" : "=f"(y) : "f"(v)); return y;
}

// Group barrier: 32 CTAs per group, all resident (128 total <= SM count).
// Per-thread __threadfence (gpu-scope release) before arrival; volatile
// flag + fence on wake. Cross-block data is read via __ldcg (L2 coherent).
__device__ __forceinline__ void group_sync(int gid) {
    __threadfence();
    __syncthreads();
    if (threadIdx.x == 0) {
        const int s = gid * 64;
        unsigned g = g_bargen[s];
        if (atomicAdd(&g_barcnt[s], 1u) == GBLK - 1) {
            atomicExch(&g_barcnt[s], 0u);
            __threadfence();
            g_bargen[s] = g + 1;
        } else {
            while (g_bargen[s] == g) { __nanosleep(32); }
        }
        __threadfence();
    }
    __syncthreads();
}

// smem layout (float offsets)
#define WD_OFF   0        // Wdup: 24 rows x 258 f32x2 = 12384 f
#define BIG_OFF  12384    // 8192 f union: stage0 As / chunk Hs / step Ah2
#define CS_OFF   20576    // 256 f  chunk cond tile
#define CSM_OFF  20832    // 256 f  per-step cond stage (double-buffered)
#define GH_OFF   21088    // 384 f  h-side preactivations
#define SMEM_F   21472    // 85888 B

__global__ void __launch_bounds__(TPB, 1) dag_rnn_kernel(
    const float* __restrict__ x,     // (B,T,D)
    const float* __restrict__ cond,  // (B,T,T)
    const float* __restrict__ Win,   // (D,3U)
    const float* __restrict__ Wrec,  // (U,3U)
    const float* __restrict__ bias,  // (2,3U)
    float* __restrict__ out)         // (B,T,U) == H storage
{
    extern __shared__ __align__(16) float smem[];
    ull*   Wd  = (ull*)(smem + WD_OFF);   // [c][k] = {w,w}
    float* BIG = smem + BIG_OFF;
    ull*   Ah2 = (ull*)BIG;               // [bp][k] = {A[2bp,k], A[2bp+1,k]}
    float* Cs  = smem + CS_OFF;
    float* Csm = smem + CSM_OFF;          // 2 x 128
    float* Gh  = smem + GH_OFF;

    const int tid = threadIdx.x;
    const int blk = blockIdx.x;
    const int gid = blk >> 5;          // barrier group (16 batches each)

    const int b0 = (blk >> 5) * 16;    // batch tile
    const int u0 = (blk & 31) * 8;     // u tile

    // hg-GEMM identity (tid<192): 8 batch-pairs x 24 cols
    const int c  = tid % 24;
    const int bp = tid / 24;
    const int gcol = (c >> 3) * UU + u0 + (c & 7);
    float bh = 0.f;
    if (tid < 192) bh = bias[G3 + gcol];

    // ---- preload Wrec slice, duplicated pairs: Wd[c][k] = {w,w} ----
    for (int idx = tid; idx < 24 * UU; idx += TPB) {
        int cc = idx >> 8, k = idx & 255;
        int colc = (cc >> 3) * UU + u0 + (cc & 7);
        float w = Wrec[(size_t)k * G3 + colc];
        Wd[cc * WST + k] = pack2(w, w);
    }

    // ================= stage 0: g_xg = x @ Win + bias0 =================
    // block writes (b,t)-rows [blk*256, blk*256+256)  -> group-local
    {
        float* As = BIG;                       // 32 x 128
        const float bz  = bias[tid];
        const float br  = bias[UU + tid];
        const float bhh = bias[2 * UU + tid];
        const int row0 = blk * 256;
        for (int rt = 0; rt < 8; ++rt) {
            const int rbase = row0 + rt * 32;
            __syncthreads();
            for (int idx = tid; idx < 32 * DD; idx += TPB)
                As[idx] = x[(size_t)rbase * DD + idx];
            __syncthreads();
            for (int rs = 0; rs < 4; ++rs) {
                float a0[8], a1[8], a2[8];
                #pragma unroll
                for (int r = 0; r < 8; ++r) { a0[r] = 0.f; a1[r] = 0.f; a2[r] = 0.f; }
                const float* asr = As + (rs * 8) * DD;
                #pragma unroll 4
                for (int k = 0; k < DD; ++k) {
                    float w0 = __ldg(&Win[(size_t)k * G3 + tid]);
                    float w1 = __ldg(&Win[(size_t)k * G3 + UU + tid]);
                    float w2 = __ldg(&Win[(size_t)k * G3 + 2 * UU + tid]);
                    #pragma unroll
                    for (int r = 0; r < 8; ++r) {
                        float a = asr[r * DD + k];
                        a0[r] += a * w0; a1[r] += a * w1; a2[r] += a * w2;
                    }
                }
                #pragma unroll
                for (int r = 0; r < 8; ++r) {
                    size_t ro = (size_t)(rbase + rs * 8 + r) * G3;
                    g_xg[ro + tid]          = a0[r] + bz;
                    g_xg[ro + UU + tid]     = a1[r] + br;
                    g_xg[ro + 2 * UU + tid] = a2[r] + bhh;
                }
            }
        }
    }
    group_sync(gid);

    const float invT = 1.0f / (float)TT;

    // persistent gate-input registers (tid<128), prefetched one step ahead
    float xz = 0.f, xr = 0.f, xh = 0.f;
    if (tid < 128) {
        const int uq = tid & 7, bb2 = tid >> 3;
        const size_t xo = ((size_t)(b0 + bb2) * TT + 0) * G3 + u0 + uq;
        xz = __ldg(&g_xg[xo]);
        xr = __ldg(&g_xg[xo + UU]);
        xh = __ldg(&g_xg[xo + 2 * UU]);
    }

    for (int c0 = 0; c0 < TT; c0 += CH) {
        // ---------- chunk-base GEMM: 16 group batches x 2 j-halves ----------
        if (c0 > 0) {
            float* Hs = BIG;                   // up to 32 x 256
            const int cb   = blk >> 1;         // in [16*gid, 16*gid+16)
            const int jh   = blk & 1;
            const int kb   = c0 >> 1;
            const int jbeg = jh * kb;
            const float* hrow = out  + ((size_t)cb * TT + jbeg) * UU;
            const float* crow = cond + ((size_t)cb * TT + c0) * TT + jbeg;

            float acc[2][8];
            #pragma unroll
            for (int a = 0; a < 2; ++a)
                #pragma unroll
                for (int q = 0; q < 8; ++q) acc[a][q] = 0.f;

            const int lg = tid >> 5;
            const int ug = tid & 31;

            for (int jt = 0; jt < kb; jt += 32) {
                const int jn = (kb - jt < 32) ? (kb - jt) : 32;
                __syncthreads();
                for (int idx = tid; idx < jn * UU; idx += TPB)
                    Hs[idx] = __ldcg(&hrow[(size_t)jt * UU + idx]);
                {
                    int l = tid >> 5, jj = tid & 31;
                    if (jj < jn)
                        Cs[jj * CH + l] = __ldg(&crow[(size_t)l * TT + jt + jj]);
                }
                __syncthreads();
                if (tid < 128) {
                    for (int jj = 0; jj < jn; ++jj) {
                        float cv0 = Cs[jj * CH + lg];
                        float cv1 = Cs[jj * CH + lg + 4];
                        const float4* h4 = (const float4*)&Hs[jj * UU + ug * 8];
                        float4 ha = h4[0], hb2 = h4[1];
                        acc[0][0] += cv0 * ha.x;  acc[0][1] += cv0 * ha.y;
                        acc[0][2] += cv0 * ha.z;  acc[0][3] += cv0 * ha.w;
                        acc[0][4] += cv0 * hb2.x; acc[0][5] += cv0 * hb2.y;
                        acc[0][6] += cv0 * hb2.z; acc[0][7] += cv0 * hb2.w;
                        acc[1][0] += cv1 * ha.x;  acc[1][1] += cv1 * ha.y;
                        acc[1][2] += cv1 * ha.z;  acc[1][3] += cv1 * ha.w;
                        acc[1][4] += cv1 * hb2.x; acc[1][5] += cv1 * hb2.y;
                        acc[1][6] += cv1 * hb2.z; acc[1][7] += cv1 * hb2.w;
                    }
                }
            }
            if (tid < 128) {
                #pragma unroll
                for (int li = 0; li < 2; ++li) {
                    const int l = lg + li * 4;
                    float* dst = &g_basep[jh][cb][l][ug * 8];
                    ((float4*)dst)[0] = make_float4(acc[li][0], acc[li][1],
                                                    acc[li][2], acc[li][3]);
                    ((float4*)dst)[1] = make_float4(acc[li][4], acc[li][5],
                                                    acc[li][6], acc[li][7]);
                }
            }
            group_sync(gid);
        }

        // ---------------- sequential steps within chunk ----------------
        for (int l = 0; l < CH; ++l) {
            const int i = c0 + l;
            const int lnext = (l < CH - 1) ? (l + 1) : 0;  // next chunk starts at l=0
            float* CsmCur = Csm + (l & 1) * 128;
            float* CsmNxt = Csm + ((l + 1) & 1) * 128;

            // ---- correction + base -> Ah2 (128 u-pairs x 2 bb-halves) ----
            {
                const int u2  = tid & 127;
                const int bbh = tid >> 7;
                float2 acc[8];
                if (c0 > 0) {
                    #pragma unroll
                    for (int r = 0; r < 8; ++r) {
                        const int bb = bbh * 8 + r;
                        float2 p0 = __ldcg((const float2*)&g_basep[0][b0 + bb][l][2 * u2]);
                        float2 p1 = __ldcg((const float2*)&g_basep[1][b0 + bb][l][2 * u2]);
                        acc[r].x = p0.x + p1.x;
                        acc[r].y = p0.y + p1.y;
                    }
                } else {
                    #pragma unroll
                    for (int r = 0; r < 8; ++r) acc[r] = make_float2(0.f, 0.f);
                }
                for (int jj = 0; jj < l; ++jj) {
                    #pragma unroll
                    for (int r = 0; r < 8; ++r) {
                        const int bb = bbh * 8 + r;
                        float cv = CsmCur[jj * 16 + bb];
                        float2 h = __ldcg((const float2*)
                            &out[((size_t)(b0 + bb) * TT + c0 + jj) * UU + 2 * u2]);
                        acc[r].x += cv * h.x;
                        acc[r].y += cv * h.y;
                    }
                }
                float* ahf = (float*)Ah2;
                #pragma unroll
                for (int r = 0; r < 8; ++r) {
                    const int bb = bbh * 8 + r;
                    const int wo = ((bb >> 1) * WST) * 2 + (bb & 1);
                    ahf[wo + 2 * (2 * u2)]     = acc[r].x * invT;
                    ahf[wo + 2 * (2 * u2 + 1)] = acc[r].y * invT;
                }
            }
            __syncthreads();

            // ---- prefetch next step's cond + gate inputs (latency hides under GEMM) ----
            float cnext = 0.f, xzp = 0.f, xrp = 0.f, xhp = 0.f;
            if (tid < 128) {
                const int jj = tid >> 4, bb = tid & 15;
                if (jj < lnext)
                    cnext = __ldg(&cond[((size_t)(b0 + bb) * TT + (i + 1)) * TT
                                        + (c0 + (l == CH - 1 ? CH : 0)) + jj]);
                if (i + 1 < TT) {
                    const int uq = tid & 7, bb2 = tid >> 3;
                    const size_t xo = ((size_t)(b0 + bb2) * TT + (i + 1)) * G3 + u0 + uq;
                    xzp = __ldg(&g_xg[xo]);
                    xrp = __ldg(&g_xg[xo + UU]);
                    xhp = __ldg(&g_xg[xo + 2 * UU]);
                }
            }

            // ---- hg = next @ Wrec via packed FFMA2 (192 threads) ----
            if (tid < 192) {
                const ull* wa = Wd  + c  * WST;
                const ull* aa = Ah2 + bp * WST;
                ull acc0 = 0ull, acc1 = 0ull, acc2 = 0ull, acc3 = 0ull;
                #pragma unroll 8
                for (int k2 = 0; k2 < 64; ++k2) {
                    ulonglong2 w0 = ((const ulonglong2*)wa)[2 * k2];
                    ulonglong2 a0 = ((const ulonglong2*)aa)[2 * k2];
                    ulonglong2 w1 = ((const ulonglong2*)wa)[2 * k2 + 1];
                    ulonglong2 a1 = ((const ulonglong2*)aa)[2 * k2 + 1];
                    FMA2(acc0, a0.x, w0.x);
                    FMA2(acc1, a0.y, w0.y);
                    FMA2(acc2, a1.x, w1.x);
                    FMA2(acc3, a1.y, w1.y);
                }
                ADD2(acc0, acc1);
                ADD2(acc2, acc3);
                ADD2(acc0, acc2);
                float g0, g1;
                unpack2(acc0, g0, g1);
                Gh[(2 * bp)     * 24 + c] = g0 + bh;
                Gh[(2 * bp + 1) * 24 + c] = g1 + bh;
            }
            __syncthreads();

            // ---- gates + output (16b x 8u = 128 threads) ----
            if (tid < 128) {
                const int uq = tid & 7, bb = tid >> 3;
                float hz = Gh[bb * 24 + uq];
                float hr = Gh[bb * 24 + 8 + uq];
                float hh = Gh[bb * 24 + 16 + uq];
                float z  = 1.0f / (1.0f + __expf(-(xz + hz)));
                float r  = 1.0f / (1.0f + __expf(-(xr + hr)));
                float hc = tanh_fast(xh + r * hh);
                float h  = ((const float*)Ah2)[((bb >> 1) * WST + u0 + uq) * 2 + (bb & 1)];
                out[((size_t)(b0 + bb) * TT + i) * UU + u0 + uq]
                    = z * h + (1.0f - z) * hc;
                // stage next step's cond into the other Csm buffer
                if ((tid >> 4) < lnext) CsmNxt[tid] = cnext;
            }
            xz = xzp; xr = xrp; xh = xhp;
            group_sync(gid);
        }
    }
}

extern "C" void kernel_launch(void* const* d_in, const int* in_sizes, int n_in,
                              void* d_out, int out_size) {
    const float* x    = (const float*)d_in[0];
    const float* cond = (const float*)d_in[1];
    const float* Win  = (const float*)d_in[2];
    const float* Wrec = (const float*)d_in[3];
    const float* bias = (const float*)d_in[4];
    float* out = (float*)d_out;

    const int smem_bytes = SMEM_F * sizeof(float);
    static bool attr_set = false;
    if (!attr_set) {
        cudaFuncSetAttribute(dag_rnn_kernel,
                             cudaFuncAttributeMaxDynamicSharedMemorySize, smem_bytes);
        attr_set = true;
    }
    dag_rnn_kernel<<<NBLK, TPB, smem_bytes>>>(x, cond, Win, Wrec, bias, out);
}